// round 1
// baseline (speedup 1.0000x reference)
#include <cuda_runtime.h>
#include <math.h>

#define B_DIM 64
#define C_DIM 64
#define K_CL 8
#define HW 12544            // 112*112
#define HW4 3136            // HW/4
#define BC (B_DIM * C_DIM)  // 4096
#define EPS 1e-6f

// Scratch (device globals — no allocation allowed)
__device__ float g_s1[BC];
__device__ float g_s2[BC];
__device__ float g_scale[BC];
__device__ float g_bias[BC];

// ---------------------------------------------------------------------------
// Kernel 1: per-(b,c) plane moments. One block per plane, float4 streaming.
// ---------------------------------------------------------------------------
__global__ __launch_bounds__(256) void k_moments(const float* __restrict__ x) {
    const int bc = blockIdx.x;
    const float4* __restrict__ p =
        reinterpret_cast<const float4*>(x + (size_t)bc * HW);

    float s1 = 0.f, s2 = 0.f;
#pragma unroll 4
    for (int i = threadIdx.x; i < HW4; i += 256) {
        float4 v = p[i];
        s1 += (v.x + v.y) + (v.z + v.w);
        s2 += (v.x * v.x + v.y * v.y) + (v.z * v.z + v.w * v.w);
    }

    // warp reduce
#pragma unroll
    for (int off = 16; off > 0; off >>= 1) {
        s1 += __shfl_down_sync(0xffffffffu, s1, off);
        s2 += __shfl_down_sync(0xffffffffu, s2, off);
    }

    __shared__ float sh1[8], sh2[8];
    const int lane = threadIdx.x & 31;
    const int wid = threadIdx.x >> 5;
    if (lane == 0) { sh1[wid] = s1; sh2[wid] = s2; }
    __syncthreads();
    if (wid == 0) {
        s1 = (lane < 8) ? sh1[lane] : 0.f;
        s2 = (lane < 8) ? sh2[lane] : 0.f;
#pragma unroll
        for (int off = 4; off > 0; off >>= 1) {
            s1 += __shfl_down_sync(0xffffffffu, s1, off);
            s2 += __shfl_down_sync(0xffffffffu, s2, off);
        }
        if (lane == 0) { g_s1[bc] = s1; g_s2[bc] = s2; }
    }
}

// ---------------------------------------------------------------------------
// Kernel 2: single block. argmax -> cid, segment sums -> cluster stats,
// then per-(b,c) scale/bias.
// ---------------------------------------------------------------------------
__global__ __launch_bounds__(256) void k_stats(const float* __restrict__ cluster_map,
                                               const float* __restrict__ lmda) {
    __shared__ float sh_s1[BC];
    __shared__ float sh_s2[BC];
    __shared__ float sh_cmu[K_CL * C_DIM];
    __shared__ float sh_cstd[K_CL * C_DIM];
    __shared__ float sh_lmda[B_DIM];
    __shared__ int   sh_cid[B_DIM];
    __shared__ float sh_cnt[K_CL];

    const int tid = threadIdx.x;

    // cid[b] = argmax_k cluster_map[0,b,k] (first-max tie break), lmda load
    if (tid < B_DIM) {
        const float* row = cluster_map + tid * K_CL;
        float best = row[0];
        int bi = 0;
#pragma unroll
        for (int k = 1; k < K_CL; ++k) {
            float v = row[k];
            if (v > best) { best = v; bi = k; }
        }
        sh_cid[tid] = bi;
        sh_lmda[tid] = lmda[tid];
    }

    // load s1/s2 into smem
    for (int i = tid; i < BC; i += 256) {
        sh_s1[i] = g_s1[i];
        sh_s2[i] = g_s2[i];
    }
    __syncthreads();

    // counts per cluster
    if (tid < K_CL) {
        float c = 0.f;
#pragma unroll
        for (int b = 0; b < B_DIM; ++b)
            if (sh_cid[b] == tid) c += 1.f;
        sh_cnt[tid] = c;
    }
    __syncthreads();

    // cluster stats: one thread per (k,c), two passes (512 entries / 256 thr)
    for (int kc = tid; kc < K_CL * C_DIM; kc += 256) {
        const int k = kc >> 6;   // / C_DIM
        const int c = kc & 63;   // % C_DIM
        float cs1 = 0.f, cs2 = 0.f;
#pragma unroll
        for (int b = 0; b < B_DIM; ++b) {
            if (sh_cid[b] == k) {
                cs1 += sh_s1[b * C_DIM + c];
                cs2 += sh_s2[b * C_DIM + c];
            }
        }
        float n_k = fmaxf(sh_cnt[k] * (float)HW, 1.0f);
        float mu = cs1 / n_k;
        float var = (cs2 - n_k * mu * mu) / fmaxf(n_k - 1.0f, 1.0f);
        sh_cmu[kc] = mu;
        sh_cstd[kc] = sqrtf(var + EPS);
    }
    __syncthreads();

    // per-(b,c) fused affine parameters
    const float inv_n = 1.0f / (float)HW;
    const float inv_nm1 = 1.0f / (float)(HW - 1);
    for (int bc = tid; bc < BC; bc += 256) {
        const int b = bc >> 6;
        const int c = bc & 63;
        float smu = sh_s1[bc] * inv_n;
        float svar = (sh_s2[bc] - (float)HW * smu * smu) * inv_nm1;
        float sstd = sqrtf(svar + EPS);
        const int k = sh_cid[b];
        float cmu = sh_cmu[k * C_DIM + c];
        float cstd = sh_cstd[k * C_DIM + c];
        float l = sh_lmda[b];
        float std_mix = sstd * l + cstd * (1.0f - l);
        float mu_mix = smu * l + cmu * (1.0f - l);
        float scale = std_mix / sstd;
        g_scale[bc] = scale;
        g_bias[bc] = mu_mix - smu * scale;
    }
}

// ---------------------------------------------------------------------------
// Kernel 3: out = x * scale[bc] + bias[bc]. One block per plane, float4.
// ---------------------------------------------------------------------------
__global__ __launch_bounds__(256) void k_apply(const float* __restrict__ x,
                                               float* __restrict__ out) {
    const int bc = blockIdx.x;
    const float scale = g_scale[bc];
    const float bias = g_bias[bc];
    const float4* __restrict__ px =
        reinterpret_cast<const float4*>(x + (size_t)bc * HW);
    float4* __restrict__ po = reinterpret_cast<float4*>(out + (size_t)bc * HW);

#pragma unroll 4
    for (int i = threadIdx.x; i < HW4; i += 256) {
        float4 v = px[i];
        v.x = fmaf(v.x, scale, bias);
        v.y = fmaf(v.y, scale, bias);
        v.z = fmaf(v.z, scale, bias);
        v.w = fmaf(v.w, scale, bias);
        po[i] = v;
    }
}

extern "C" void kernel_launch(void* const* d_in, const int* in_sizes, int n_in,
                              void* d_out, int out_size) {
    const float* x = (const float*)d_in[0];            // [64,64,112,112]
    const float* cluster_map = (const float*)d_in[1];  // [1,64,8]
    const float* lmda = (const float*)d_in[2];         // [64,1,1,1]
    float* out = (float*)d_out;

    k_moments<<<BC, 256>>>(x);
    k_stats<<<1, 256>>>(cluster_map, lmda);
    k_apply<<<BC, 256>>>(x, out);
}

// round 2
// speedup vs baseline: 1.0794x; 1.0794x over previous
#include <cuda_runtime.h>
#include <math.h>

#define B_DIM 64
#define C_DIM 64
#define K_CL 8
#define HW 12544            // 112*112
#define HW4 3136            // HW/4
#define BC (B_DIM * C_DIM)  // 4096
#define EPS 1e-6f

// Scratch (device globals — no allocation allowed)
__device__ float g_s1[BC];
__device__ float g_s2[BC];
__device__ float g_scale[BC];
__device__ float g_bias[BC];

// ---------------------------------------------------------------------------
// Kernel 1: per-(b,c) plane moments. One block per plane, float4 streaming.
// Front-to-back: leaves the TAIL of x resident in L2 for k_apply.
// ---------------------------------------------------------------------------
__global__ __launch_bounds__(256) void k_moments(const float* __restrict__ x) {
    const int bc = blockIdx.x;
    const float4* __restrict__ p =
        reinterpret_cast<const float4*>(x + (size_t)bc * HW);

    float s1 = 0.f, s2 = 0.f;
#pragma unroll 4
    for (int i = threadIdx.x; i < HW4; i += 256) {
        float4 v = p[i];
        s1 += (v.x + v.y) + (v.z + v.w);
        s2 += (v.x * v.x + v.y * v.y) + (v.z * v.z + v.w * v.w);
    }

    // warp reduce
#pragma unroll
    for (int off = 16; off > 0; off >>= 1) {
        s1 += __shfl_down_sync(0xffffffffu, s1, off);
        s2 += __shfl_down_sync(0xffffffffu, s2, off);
    }

    __shared__ float sh1[8], sh2[8];
    const int lane = threadIdx.x & 31;
    const int wid = threadIdx.x >> 5;
    if (lane == 0) { sh1[wid] = s1; sh2[wid] = s2; }
    __syncthreads();
    if (wid == 0) {
        s1 = (lane < 8) ? sh1[lane] : 0.f;
        s2 = (lane < 8) ? sh2[lane] : 0.f;
#pragma unroll
        for (int off = 4; off > 0; off >>= 1) {
            s1 += __shfl_down_sync(0xffffffffu, s1, off);
            s2 += __shfl_down_sync(0xffffffffu, s2, off);
        }
        if (lane == 0) { g_s1[bc] = s1; g_s2[bc] = s2; }
    }
}

// ---------------------------------------------------------------------------
// Kernel 2: single block. argmax -> cid, segment sums -> cluster stats,
// then per-(b,c) fused scale/bias.
// ---------------------------------------------------------------------------
__global__ __launch_bounds__(256) void k_stats(const float* __restrict__ cluster_map,
                                               const float* __restrict__ lmda) {
    __shared__ float sh_s1[BC];
    __shared__ float sh_s2[BC];
    __shared__ float sh_cmu[K_CL * C_DIM];
    __shared__ float sh_cstd[K_CL * C_DIM];
    __shared__ float sh_lmda[B_DIM];
    __shared__ int   sh_cid[B_DIM];
    __shared__ float sh_cnt[K_CL];

    const int tid = threadIdx.x;

    if (tid < B_DIM) {
        const float* row = cluster_map + tid * K_CL;
        float best = row[0];
        int bi = 0;
#pragma unroll
        for (int k = 1; k < K_CL; ++k) {
            float v = row[k];
            if (v > best) { best = v; bi = k; }
        }
        sh_cid[tid] = bi;
        sh_lmda[tid] = lmda[tid];
    }

    for (int i = tid; i < BC; i += 256) {
        sh_s1[i] = g_s1[i];
        sh_s2[i] = g_s2[i];
    }
    __syncthreads();

    if (tid < K_CL) {
        float c = 0.f;
#pragma unroll
        for (int b = 0; b < B_DIM; ++b)
            if (sh_cid[b] == tid) c += 1.f;
        sh_cnt[tid] = c;
    }
    __syncthreads();

    for (int kc = tid; kc < K_CL * C_DIM; kc += 256) {
        const int k = kc >> 6;
        const int c = kc & 63;
        float cs1 = 0.f, cs2 = 0.f;
#pragma unroll
        for (int b = 0; b < B_DIM; ++b) {
            if (sh_cid[b] == k) {
                cs1 += sh_s1[b * C_DIM + c];
                cs2 += sh_s2[b * C_DIM + c];
            }
        }
        float n_k = fmaxf(sh_cnt[k] * (float)HW, 1.0f);
        float mu = cs1 / n_k;
        float var = (cs2 - n_k * mu * mu) / fmaxf(n_k - 1.0f, 1.0f);
        sh_cmu[kc] = mu;
        sh_cstd[kc] = sqrtf(var + EPS);
    }
    __syncthreads();

    const float inv_n = 1.0f / (float)HW;
    const float inv_nm1 = 1.0f / (float)(HW - 1);
    for (int bc = tid; bc < BC; bc += 256) {
        const int b = bc >> 6;
        const int c = bc & 63;
        float smu = sh_s1[bc] * inv_n;
        float svar = (sh_s2[bc] - (float)HW * smu * smu) * inv_nm1;
        float sstd = sqrtf(svar + EPS);
        const int k = sh_cid[b];
        float cmu = sh_cmu[k * C_DIM + c];
        float cstd = sh_cstd[k * C_DIM + c];
        float l = sh_lmda[b];
        float std_mix = sstd * l + cstd * (1.0f - l);
        float mu_mix = smu * l + cmu * (1.0f - l);
        float scale = std_mix / sstd;
        g_scale[bc] = scale;
        g_bias[bc] = mu_mix - smu * scale;
    }
}

// ---------------------------------------------------------------------------
// Kernel 3: out = x * scale[bc] + bias[bc].
// REVERSE plane order: first wave reads the x planes k_moments most recently
// streamed (still L2-resident, ~120MB). Output stores use .cs (evict-first)
// so the write stream doesn't evict warm, not-yet-read x planes.
// ---------------------------------------------------------------------------
__global__ __launch_bounds__(256) void k_apply(const float* __restrict__ x,
                                               float* __restrict__ out) {
    const int bc = (BC - 1) - blockIdx.x;   // reverse order for L2 tail reuse
    const float scale = g_scale[bc];
    const float bias = g_bias[bc];
    const float4* __restrict__ px =
        reinterpret_cast<const float4*>(x + (size_t)bc * HW);
    float4* __restrict__ po = reinterpret_cast<float4*>(out + (size_t)bc * HW);

#pragma unroll 4
    for (int i = threadIdx.x; i < HW4; i += 256) {
        float4 v = px[i];
        v.x = fmaf(v.x, scale, bias);
        v.y = fmaf(v.y, scale, bias);
        v.z = fmaf(v.z, scale, bias);
        v.w = fmaf(v.w, scale, bias);
        __stcs(&po[i], v);  // streaming store: don't pollute L2
    }
}

extern "C" void kernel_launch(void* const* d_in, const int* in_sizes, int n_in,
                              void* d_out, int out_size) {
    const float* x = (const float*)d_in[0];            // [64,64,112,112]
    const float* cluster_map = (const float*)d_in[1];  // [1,64,8]
    const float* lmda = (const float*)d_in[2];         // [64,1,1,1]
    float* out = (float*)d_out;

    k_moments<<<BC, 256>>>(x);
    k_stats<<<1, 256>>>(cluster_map, lmda);
    k_apply<<<BC, 256>>>(x, out);
}